// round 14
// baseline (speedup 1.0000x reference)
#include <cuda_runtime.h>
#include <cuda_bf16.h>
#include <cstdint>

#define ULL unsigned long long

// ---------------- scratch (static device globals; no dynamic alloc) ----------------
// xg layout: [256][1024][100][4]  (per unit u: contiguous i,f,g,o quad)
__device__ float  g_xg[104857600];
// W2hh layout: [k][2u+p] pairs; p=0 -> (W_i[u][k], W_f[u][k]); p=1 -> (W_g[u][k], W_o[u][k])
__device__ ULL    g_W2hh[100 * 200];
// B fragments for mma.sync m16n8k16 bf16: [ntile 0..49][kstep 0..3][lane 0..31]
__device__ uint4  g_Bf[50 * 4 * 32];
__device__ float4 g_bias4[100];         // per-unit (b_i, b_f, b_g, b_o), b_ih + b_hh

// ---------------- f32x2 packed helpers ----------------
__device__ __forceinline__ ULL pk(float x, float y) {
    ULL r; asm("mov.b64 %0,{%1,%2};" : "=l"(r) : "f"(x), "f"(y)); return r;
}
__device__ __forceinline__ float2 upk(ULL v) {
    float2 r; asm("mov.b64 {%0,%1},%2;" : "=f"(r.x), "=f"(r.y) : "l"(v)); return r;
}
__device__ __forceinline__ ULL fma2(ULL a, ULL b, ULL c) {
    ULL d; asm("fma.rn.f32x2 %0,%1,%2,%3;" : "=l"(d) : "l"(a), "l"(b), "l"(c)); return d;
}
__device__ __forceinline__ ULL add2(ULL a, ULL b) {
    ULL d; asm("add.rn.f32x2 %0,%1,%2;" : "=l"(d) : "l"(a), "l"(b)); return d;
}
__device__ __forceinline__ float sigf(float x) {
    float e = __expf(-x);
    return __fdividef(1.f, 1.f + e);
}
__device__ __forceinline__ float tahf(float x) {
    float e = __expf(2.f * x);
    return 1.f - __fdividef(2.f, e + 1.f);
}

// ---------------- mma / ldmatrix helpers (sm_80 baseline PTX, valid on sm_103) ----------------
__device__ __forceinline__ uint32_t bf2u(float a, float b) {
    __nv_bfloat162 h = __float22bfloat162_rn(make_float2(a, b));
    return *(uint32_t*)&h;
}
__device__ __forceinline__ void mma_bf16(float* c, const uint32_t* a, uint32_t b0, uint32_t b1) {
    asm volatile("mma.sync.aligned.m16n8k16.row.col.f32.bf16.bf16.f32 "
        "{%0,%1,%2,%3}, {%4,%5,%6,%7}, {%8,%9}, {%0,%1,%2,%3};"
        : "+f"(c[0]), "+f"(c[1]), "+f"(c[2]), "+f"(c[3])
        : "r"(a[0]), "r"(a[1]), "r"(a[2]), "r"(a[3]), "r"(b0), "r"(b1));
}
__device__ __forceinline__ void ldm4(uint32_t* r, uint32_t addr) {
    asm volatile("ldmatrix.sync.aligned.m8n8.x4.shared.b16 {%0,%1,%2,%3}, [%4];"
        : "=r"(r[0]), "=r"(r[1]), "=r"(r[2]), "=r"(r[3]) : "r"(addr));
}
__device__ __forceinline__ uint32_t smem_u32(const void* p) {
    uint32_t a;
    asm("{ .reg .u64 t; cvta.to.shared.u64 t, %1; cvt.u32.u64 %0, t; }" : "=r"(a) : "l"(p));
    return a;
}

// ---------------- prep: repack weights ----------------
__global__ void prep_kernel(const float* __restrict__ Wih, const float* __restrict__ Whh,
                            const float* __restrict__ bih, const float* __restrict__ bhh) {
    int tid = blockIdx.x * blockDim.x + threadIdx.x;
    int stride = gridDim.x * blockDim.x;
    for (int i = tid; i < 100 * 200; i += stride) {
        int k = i / 200, ju = i % 200;
        int u = ju >> 1, p = ju & 1;
        ULL v;
        if (p == 0) v = pk(Whh[(u)       * 100 + k], Whh[(100 + u) * 100 + k]);  // (i,f)
        else        v = pk(Whh[(200 + u) * 100 + k], Whh[(300 + u) * 100 + k]);  // (g,o)
        g_W2hh[i] = v;
    }
    for (int s = tid; s < 6400; s += stride) {
        int ntg = s >> 7, ks = (s >> 5) & 3, l = s & 31;
        int n = ntg * 8 + (l >> 2);
        int u = n >> 2, c = n & 3;
        const float* wr = Wih + (c * 100 + u) * 64;
        int kb = ks * 16 + (l & 3) * 2;
        float w00 = wr[kb], w01 = wr[kb + 1], w10 = wr[kb + 8], w11 = wr[kb + 9];
        __nv_bfloat16 h00 = __float2bfloat16(w00), h01 = __float2bfloat16(w01);
        __nv_bfloat16 h10 = __float2bfloat16(w10), h11 = __float2bfloat16(w11);
        uint4 o;
        o.x = bf2u(w00, w01);
        o.y = bf2u(w10, w11);
        o.z = bf2u(w00 - __bfloat162float(h00), w01 - __bfloat162float(h01));
        o.w = bf2u(w10 - __bfloat162float(h10), w11 - __bfloat162float(h11));
        g_Bf[s] = o;
    }
    for (int i = tid; i < 100; i += stride) {
        float4 v;
        v.x = bih[i]       + bhh[i];
        v.y = bih[100 + i] + bhh[100 + i];
        v.z = bih[200 + i] + bhh[200 + i];
        v.w = bih[300 + i] + bhh[300 + i];
        g_bias4[i] = v;
    }
}

// ---------------- phase 1: HMMA xgemm (bf16 hi/lo split, 3 terms) — unchanged from R13 ----------------
static constexpr int XS_BF   = 0;
static constexpr int XS_AHI  = 102400;
static constexpr int XS_ALO  = 120832;
static constexpr int XS_BIAS = 139264;
static constexpr int XS_TOT  = 140864;

__global__ __launch_bounds__(256, 1) void xgemm_hmma(const float* __restrict__ x) {
    extern __shared__ char smem[];
    const int tid = threadIdx.x, warp = tid >> 5, lane = tid & 31;

    {
        uint4* dst = (uint4*)(smem + XS_BF);
        for (int i = tid; i < 6400; i += 256) dst[i] = g_Bf[i];
    }
    {
        const float* bs = (const float*)g_bias4;
        float* bd = (float*)(smem + XS_BIAS);
        for (int i = tid; i < 400; i += 256) bd[i] = bs[i];
    }
    {
        const float2* xp = (const float2*)(x + (size_t)blockIdx.x * 128 * 64);
        for (int i = tid; i < 128 * 32; i += 256) {
            int r = i >> 5, k2 = i & 31;
            float2 v = xp[i];
            uint32_t hi = bf2u(v.x, v.y);
            __nv_bfloat162 hh = *(__nv_bfloat162*)&hi;
            float2 hf = __bfloat1622float2(hh);
            uint32_t lo = bf2u(v.x - hf.x, v.y - hf.y);
            *(uint32_t*)(smem + XS_AHI + r * 144 + k2 * 4) = hi;
            *(uint32_t*)(smem + XS_ALO + r * 144 + k2 * 4) = lo;
        }
    }
    __syncthreads();

    uint32_t ah[4][4], al[4][4];
    {
        uint32_t rowoff = (uint32_t)(16 * warp + (lane & 15)) * 144 + (uint32_t)(lane >> 4) * 16;
        uint32_t sbA = smem_u32(smem);
#pragma unroll
        for (int ks = 0; ks < 4; ks++) {
            ldm4(ah[ks], sbA + XS_AHI + rowoff + ks * 32);
            ldm4(al[ks], sbA + XS_ALO + rowoff + ks * 32);
        }
    }

    const float* bs = (const float*)(smem + XS_BIAS);
    const uint4* bf = (const uint4*)(smem + XS_BF);
    size_t row0 = (size_t)blockIdx.x * 128 + warp * 16 + (lane >> 2);

#pragma unroll 1
    for (int p = 0; p < 2; p++) {
        float acc[25][4];
#pragma unroll
        for (int nt = 0; nt < 25; nt++)
#pragma unroll
            for (int q = 0; q < 4; q++) acc[nt][q] = 0.f;

#pragma unroll
        for (int ks = 0; ks < 4; ks++) {
#pragma unroll
            for (int nt = 0; nt < 25; nt++) {
                uint4 b = bf[((p * 25 + nt) * 4 + ks) * 32 + lane];
                mma_bf16(acc[nt], ah[ks], b.x, b.y);
                mma_bf16(acc[nt], ah[ks], b.z, b.w);
                mma_bf16(acc[nt], al[ks], b.x, b.y);
            }
        }
#pragma unroll
        for (int nt = 0; nt < 25; nt++) {
            int col = p * 200 + nt * 8 + (lane & 3) * 2;
            float bx = bs[col], by = bs[col + 1];
            *(float2*)(g_xg + row0 * 400 + col)       = make_float2(acc[nt][0] + bx, acc[nt][1] + by);
            *(float2*)(g_xg + (row0 + 8) * 400 + col) = make_float2(acc[nt][2] + bx, acc[nt][3] + by);
        }
    }
}

// ---------------- phase 2: LSTM recurrence — quad-shfl reduce, 1 barrier/step ----------------
// 128 blocks x 400 threads. Thread (u = t>>2, q = t&3) computes the k-slice
// [25q, 25q+25) partial of unit u's (i,f)/(g,o) pairs for BOTH batches
// (W slice = 100 regs). The 4 partials per unit live in one lane QUAD ->
// 2 rounds of shfl.bfly replace the smem partial roundtrip. h is double-
// buffered in smem so ONE __syncthreads per step suffices. Lane q==0 runs
// the cell update for both batches and prefetches next step's xg quads.
__global__ __launch_bounds__(400, 1) void lstm_kernel(const float* __restrict__ h0,
                                                      const float* __restrict__ c0,
                                                      const float* __restrict__ Wfc,
                                                      const float* __restrict__ bfc,
                                                      float* __restrict__ out) {
    __shared__ __align__(16) ULL shi[2][200];   // [buf][2k+b] = pk(h_b[k], h_b[k])
    __shared__ float red[2];                    // FC reduction

    const int t  = threadIdx.x;
    const int b0 = blockIdx.x * 2;
    const int u  = t >> 2;
    const int q  = t & 3;
    const int k0 = q * 25;

    // resident W_hh slice: 25 k x 2 pairs = 50 ULL = 100 registers
    ULL wIF[25], wGO[25];
#pragma unroll
    for (int kc = 0; kc < 25; kc++) {
        wIF[kc] = g_W2hh[(k0 + kc) * 200 + 2 * u];
        wGO[kc] = g_W2hh[(k0 + kc) * 200 + 2 * u + 1];
    }

    if (t < 2) red[t] = 0.f;

    float c0r = 0.f, c1r = 0.f, h0last = 0.f, h1last = 0.f;
    float4 px0 = make_float4(0.f, 0.f, 0.f, 0.f);
    float4 px1 = px0;
    const float* xg0 = g_xg + (size_t)(b0)     * 1024 * 400 + 4 * u;
    const float* xg1 = g_xg + (size_t)(b0 + 1) * 1024 * 400 + 4 * u;
    if (q == 0) {
        float hv0 = h0[b0 * 100 + u];
        float hv1 = h0[(b0 + 1) * 100 + u];
        c0r = c0[b0 * 100 + u];
        c1r = c0[(b0 + 1) * 100 + u];
        *(ulonglong2*)&shi[0][2 * u] = make_ulonglong2(pk(hv0, hv0), pk(hv1, hv1));
        px0 = *(const float4*)xg0;
        px1 = *(const float4*)xg1;
    }
    __syncthreads();

    const unsigned mask = __activemask();   // all threads converged here (full or 16-lane warp)

    for (int step = 0; step < 1024; step++) {
        const ulonglong2* hp = ((const ulonglong2*)shi[step & 1]) + k0;
        ULL aIF0 = 0ull, aGO0 = 0ull, aIF1 = 0ull, aGO1 = 0ull;
#pragma unroll
        for (int kc = 0; kc < 25; kc++) {
            ulonglong2 hv = hp[kc];              // (b0 dup pair, b1 dup pair)
            aIF0 = fma2(wIF[kc], hv.x, aIF0);
            aGO0 = fma2(wGO[kc], hv.x, aGO0);
            aIF1 = fma2(wIF[kc], hv.y, aIF1);
            aGO1 = fma2(wGO[kc], hv.y, aGO1);
        }
        // quad reduce: lanes q^1, q^2 (never crosses the 16-lane boundary)
        aIF0 = add2(aIF0, __shfl_xor_sync(mask, aIF0, 1));
        aGO0 = add2(aGO0, __shfl_xor_sync(mask, aGO0, 1));
        aIF1 = add2(aIF1, __shfl_xor_sync(mask, aIF1, 1));
        aGO1 = add2(aGO1, __shfl_xor_sync(mask, aGO1, 1));
        aIF0 = add2(aIF0, __shfl_xor_sync(mask, aIF0, 2));
        aGO0 = add2(aGO0, __shfl_xor_sync(mask, aGO0, 2));
        aIF1 = add2(aIF1, __shfl_xor_sync(mask, aIF1, 2));
        aGO1 = add2(aGO1, __shfl_xor_sync(mask, aGO1, 2));

        if (q == 0) {
            float2 vIF0 = upk(aIF0), vGO0 = upk(aGO0);
            float2 vIF1 = upk(aIF1), vGO1 = upk(aGO1);
            float gi0 = vIF0.x + px0.x, gf0 = vIF0.y + px0.y;
            float gg0 = vGO0.x + px0.z, go0 = vGO0.y + px0.w;
            float gi1 = vIF1.x + px1.x, gf1 = vIF1.y + px1.y;
            float gg1 = vGO1.x + px1.z, go1 = vGO1.y + px1.w;
            if (step < 1023) {                   // prefetch next step's xg quads
                px0 = *(const float4*)(xg0 + (size_t)(step + 1) * 400);
                px1 = *(const float4*)(xg1 + (size_t)(step + 1) * 400);
            }
            float i0 = sigf(gi0), f0 = sigf(gf0), g0 = tahf(gg0), o0 = sigf(go0);
            float i1 = sigf(gi1), f1 = sigf(gf1), g1 = tahf(gg1), o1 = sigf(go1);
            c0r = f0 * c0r + i0 * g0;
            c1r = f1 * c1r + i1 * g1;
            float hh0 = o0 * tahf(c0r);
            float hh1 = o1 * tahf(c1r);
            h0last = hh0; h1last = hh1;
            *(ulonglong2*)&shi[(step + 1) & 1][2 * u] =
                make_ulonglong2(pk(hh0, hh0), pk(hh1, hh1));
        }
        __syncthreads();
    }

    // fused FC head: out[b] = dot(h_T[b], W_fc) + b_fc
    if (q == 0) {
        float wv = Wfc[u];
        atomicAdd(&red[0], h0last * wv);
        atomicAdd(&red[1], h1last * wv);
    }
    __syncthreads();
    if (t < 2) out[b0 + t] = red[t] + bfc[0];
}

// ---------------- launch ----------------
extern "C" void kernel_launch(void* const* d_in, const int* in_sizes, int n_in,
                              void* d_out, int out_size) {
    const float* x   = (const float*)d_in[0];
    const float* h0  = (const float*)d_in[1];
    const float* c0  = (const float*)d_in[2];
    const float* Wih = (const float*)d_in[3];
    const float* Whh = (const float*)d_in[4];
    const float* bih = (const float*)d_in[5];
    const float* bhh = (const float*)d_in[6];
    const float* Wfc = (const float*)d_in[7];
    const float* bfc = (const float*)d_in[8];
    float* out = (float*)d_out;

    cudaFuncSetAttribute(xgemm_hmma, cudaFuncAttributeMaxDynamicSharedMemorySize, XS_TOT);

    prep_kernel<<<64, 256>>>(Wih, Whh, bih, bhh);
    xgemm_hmma<<<2048, 256, XS_TOT>>>(x);
    lstm_kernel<<<128, 400>>>(h0, c0, Wfc, bfc, out);
}

// round 15
// speedup vs baseline: 1.2039x; 1.2039x over previous
#include <cuda_runtime.h>
#include <cuda_bf16.h>
#include <cstdint>

#define ULL unsigned long long

// ---------------- scratch (static device globals; no dynamic alloc) ----------------
// xg layout: [256][1024][100][4]  (per unit u: contiguous i,f,g,o quad)
__device__ float  g_xg[104857600];
// W2hh layout: [k][2u+p] pairs; p=0 -> (W_i[u][k], W_f[u][k]); p=1 -> (W_g[u][k], W_o[u][k])
__device__ ULL    g_W2hh[100 * 200];
// B fragments for mma.sync m16n8k16 bf16: [ntile 0..49][kstep 0..3][lane 0..31]
__device__ uint4  g_Bf[50 * 4 * 32];
__device__ float4 g_bias4[100];         // per-unit (b_i, b_f, b_g, b_o), b_ih + b_hh

// ---------------- f32x2 packed helpers ----------------
__device__ __forceinline__ ULL pk(float x, float y) {
    ULL r; asm("mov.b64 %0,{%1,%2};" : "=l"(r) : "f"(x), "f"(y)); return r;
}
__device__ __forceinline__ float2 upk(ULL v) {
    float2 r; asm("mov.b64 {%0,%1},%2;" : "=f"(r.x), "=f"(r.y) : "l"(v)); return r;
}
__device__ __forceinline__ ULL fma2(ULL a, ULL b, ULL c) {
    ULL d; asm("fma.rn.f32x2 %0,%1,%2,%3;" : "=l"(d) : "l"(a), "l"(b), "l"(c)); return d;
}
__device__ __forceinline__ ULL add2(ULL a, ULL b) {
    ULL d; asm("add.rn.f32x2 %0,%1,%2;" : "=l"(d) : "l"(a), "l"(b)); return d;
}
__device__ __forceinline__ float sigf(float x) {
    float e = __expf(-x);
    return __fdividef(1.f, 1.f + e);
}
__device__ __forceinline__ float tahf(float x) {
    float e = __expf(2.f * x);
    return 1.f - __fdividef(2.f, e + 1.f);
}

// ---------------- mma / ldmatrix helpers (sm_80 baseline PTX, valid on sm_103) ----------------
__device__ __forceinline__ uint32_t bf2u(float a, float b) {
    __nv_bfloat162 h = __float22bfloat162_rn(make_float2(a, b));
    return *(uint32_t*)&h;
}
__device__ __forceinline__ void mma_bf16(float* c, const uint32_t* a, uint32_t b0, uint32_t b1) {
    asm volatile("mma.sync.aligned.m16n8k16.row.col.f32.bf16.bf16.f32 "
        "{%0,%1,%2,%3}, {%4,%5,%6,%7}, {%8,%9}, {%0,%1,%2,%3};"
        : "+f"(c[0]), "+f"(c[1]), "+f"(c[2]), "+f"(c[3])
        : "r"(a[0]), "r"(a[1]), "r"(a[2]), "r"(a[3]), "r"(b0), "r"(b1));
}
__device__ __forceinline__ void ldm4(uint32_t* r, uint32_t addr) {
    asm volatile("ldmatrix.sync.aligned.m8n8.x4.shared.b16 {%0,%1,%2,%3}, [%4];"
        : "=r"(r[0]), "=r"(r[1]), "=r"(r[2]), "=r"(r[3]) : "r"(addr));
}
__device__ __forceinline__ uint32_t smem_u32(const void* p) {
    uint32_t a;
    asm("{ .reg .u64 t; cvta.to.shared.u64 t, %1; cvt.u32.u64 %0, t; }" : "=r"(a) : "l"(p));
    return a;
}

// ---------------- prep: repack weights ----------------
__global__ void prep_kernel(const float* __restrict__ Wih, const float* __restrict__ Whh,
                            const float* __restrict__ bih, const float* __restrict__ bhh) {
    int tid = blockIdx.x * blockDim.x + threadIdx.x;
    int stride = gridDim.x * blockDim.x;
    for (int i = tid; i < 100 * 200; i += stride) {
        int k = i / 200, ju = i % 200;
        int u = ju >> 1, p = ju & 1;
        ULL v;
        if (p == 0) v = pk(Whh[(u)       * 100 + k], Whh[(100 + u) * 100 + k]);  // (i,f)
        else        v = pk(Whh[(200 + u) * 100 + k], Whh[(300 + u) * 100 + k]);  // (g,o)
        g_W2hh[i] = v;
    }
    for (int s = tid; s < 6400; s += stride) {
        int ntg = s >> 7, ks = (s >> 5) & 3, l = s & 31;
        int n = ntg * 8 + (l >> 2);
        int u = n >> 2, c = n & 3;
        const float* wr = Wih + (c * 100 + u) * 64;
        int kb = ks * 16 + (l & 3) * 2;
        float w00 = wr[kb], w01 = wr[kb + 1], w10 = wr[kb + 8], w11 = wr[kb + 9];
        __nv_bfloat16 h00 = __float2bfloat16(w00), h01 = __float2bfloat16(w01);
        __nv_bfloat16 h10 = __float2bfloat16(w10), h11 = __float2bfloat16(w11);
        uint4 o;
        o.x = bf2u(w00, w01);
        o.y = bf2u(w10, w11);
        o.z = bf2u(w00 - __bfloat162float(h00), w01 - __bfloat162float(h01));
        o.w = bf2u(w10 - __bfloat162float(h10), w11 - __bfloat162float(h11));
        g_Bf[s] = o;
    }
    for (int i = tid; i < 100; i += stride) {
        float4 v;
        v.x = bih[i]       + bhh[i];
        v.y = bih[100 + i] + bhh[100 + i];
        v.z = bih[200 + i] + bhh[200 + i];
        v.w = bih[300 + i] + bhh[300 + i];
        g_bias4[i] = v;
    }
}

// ---------------- phase 1: HMMA xgemm (bf16 hi/lo split, 3 terms) ----------------
static constexpr int XS_BF   = 0;
static constexpr int XS_AHI  = 102400;
static constexpr int XS_ALO  = 120832;
static constexpr int XS_BIAS = 139264;
static constexpr int XS_TOT  = 140864;

__global__ __launch_bounds__(256, 1) void xgemm_hmma(const float* __restrict__ x) {
    extern __shared__ char smem[];
    const int tid = threadIdx.x, warp = tid >> 5, lane = tid & 31;

    {
        uint4* dst = (uint4*)(smem + XS_BF);
        for (int i = tid; i < 6400; i += 256) dst[i] = g_Bf[i];
    }
    {
        const float* bs = (const float*)g_bias4;
        float* bd = (float*)(smem + XS_BIAS);
        for (int i = tid; i < 400; i += 256) bd[i] = bs[i];
    }
    {
        const float2* xp = (const float2*)(x + (size_t)blockIdx.x * 128 * 64);
        for (int i = tid; i < 128 * 32; i += 256) {
            int r = i >> 5, k2 = i & 31;
            float2 v = xp[i];
            uint32_t hi = bf2u(v.x, v.y);
            __nv_bfloat162 hh = *(__nv_bfloat162*)&hi;
            float2 hf = __bfloat1622float2(hh);
            uint32_t lo = bf2u(v.x - hf.x, v.y - hf.y);
            *(uint32_t*)(smem + XS_AHI + r * 144 + k2 * 4) = hi;
            *(uint32_t*)(smem + XS_ALO + r * 144 + k2 * 4) = lo;
        }
    }
    __syncthreads();

    uint32_t ah[4][4], al[4][4];
    {
        uint32_t rowoff = (uint32_t)(16 * warp + (lane & 15)) * 144 + (uint32_t)(lane >> 4) * 16;
        uint32_t sbA = smem_u32(smem);
#pragma unroll
        for (int ks = 0; ks < 4; ks++) {
            ldm4(ah[ks], sbA + XS_AHI + rowoff + ks * 32);
            ldm4(al[ks], sbA + XS_ALO + rowoff + ks * 32);
        }
    }

    const float* bs = (const float*)(smem + XS_BIAS);
    const uint4* bf = (const uint4*)(smem + XS_BF);
    size_t row0 = (size_t)blockIdx.x * 128 + warp * 16 + (lane >> 2);

#pragma unroll 1
    for (int p = 0; p < 2; p++) {
        float acc[25][4];
#pragma unroll
        for (int nt = 0; nt < 25; nt++)
#pragma unroll
            for (int q = 0; q < 4; q++) acc[nt][q] = 0.f;

#pragma unroll
        for (int ks = 0; ks < 4; ks++) {
#pragma unroll
            for (int nt = 0; nt < 25; nt++) {
                uint4 b = bf[((p * 25 + nt) * 4 + ks) * 32 + lane];
                mma_bf16(acc[nt], ah[ks], b.x, b.y);
                mma_bf16(acc[nt], ah[ks], b.z, b.w);
                mma_bf16(acc[nt], al[ks], b.x, b.y);
            }
        }
#pragma unroll
        for (int nt = 0; nt < 25; nt++) {
            int col = p * 200 + nt * 8 + (lane & 3) * 2;
            float bx = bs[col], by = bs[col + 1];
            *(float2*)(g_xg + row0 * 400 + col)       = make_float2(acc[nt][0] + bx, acc[nt][1] + by);
            *(float2*)(g_xg + (row0 + 8) * 400 + col) = make_float2(acc[nt][2] + bx, acc[nt][3] + by);
        }
    }
}

// no-op: makes the launch cycle length 4 so ncu's capture window (which landed
// on prep_kernel every round with a 3-kernel cycle) lands on lstm_kernel.
__global__ void align_kernel() {}

// ---------------- phase 2: sequential LSTM recurrence + fused FC head ----------------
// (R13 structure — proven 1088 us.) 128 blocks x 512 threads; thread
// (kk=t/100, u=t%100) does k-slice [20kk,20kk+20) of unit u's gate pairs for
// both batches, W slice in 80 regs, h broadcast via LDS.128 dup-pairs.
// Pointwise threads (t<200) prefetch xg FIRST (overlaps DRAM with the LDS
// reduce), then reduce 5 partials and run the cell update. Step loop
// unrolled x2 so buffer indices are compile-time.
__global__ __launch_bounds__(512, 1) void lstm_kernel(const float* __restrict__ h0,
                                                      const float* __restrict__ c0,
                                                      const float* __restrict__ Wfc,
                                                      const float* __restrict__ bfc,
                                                      float* __restrict__ out) {
    __shared__ __align__(16) ULL shi[200];            // [k][b]: shi[2k+b] = pk(h_b[k], h_b[k])
    __shared__ __align__(16) float4 part4[5 * 2 * 100];  // [kk][b][u] = (i,f,g,o) partial
    __shared__ float red[2];                          // FC reduction

    const int t  = threadIdx.x;
    const int b0 = blockIdx.x * 2;

    const bool mv = (t < 500);
    const int kk = t / 100;
    const int u  = t % 100;
    const int k0 = kk * 20;

    ULL wIF[20], wGO[20];
    if (mv) {
#pragma unroll
        for (int kc = 0; kc < 20; kc++) {
            wIF[kc] = g_W2hh[(k0 + kc) * 200 + 2 * u];
            wGO[kc] = g_W2hh[(k0 + kc) * 200 + 2 * u + 1];
        }
    }

    const int ub = (t < 100) ? 0 : 1;
    const int uu = t - ub * 100;

    if (t < 2) red[t] = 0.f;

    float c_reg = 0.f, h_last = 0.f;
    float4 px = make_float4(0.f, 0.f, 0.f, 0.f);
    const float* xgb = g_xg;
    if (t < 200) {
        float hv = h0[(b0 + ub) * 100 + uu];
        c_reg    = c0[(b0 + ub) * 100 + uu];
        shi[2 * uu + ub] = pk(hv, hv);
        xgb = g_xg + (size_t)(b0 + ub) * 1024 * 400 + 4 * uu;
        px = *(const float4*)xgb;
    }
    __syncthreads();

    float4* pb0 = part4 + kk * 200 + u;
    float4* pb1 = pb0 + 100;
    const ulonglong2* hp = ((const ulonglong2*)shi) + k0;

#pragma unroll 2
    for (int step = 0; step < 1024; step++) {
        if (mv) {
            ULL aIF0 = 0ull, aGO0 = 0ull, aIF1 = 0ull, aGO1 = 0ull;
#pragma unroll
            for (int kc = 0; kc < 20; kc++) {
                ulonglong2 hv = hp[kc];
                aIF0 = fma2(wIF[kc], hv.x, aIF0);
                aGO0 = fma2(wGO[kc], hv.x, aGO0);
                aIF1 = fma2(wIF[kc], hv.y, aIF1);
                aGO1 = fma2(wGO[kc], hv.y, aGO1);
            }
            float2 pif = upk(aIF0), pgo = upk(aGO0);
            *pb0 = make_float4(pif.x, pif.y, pgo.x, pgo.y);
            pif = upk(aIF1); pgo = upk(aGO1);
            *pb1 = make_float4(pif.x, pif.y, pgo.x, pgo.y);
        }
        __syncthreads();
        if (t < 200) {
            // prefetch next step's xg quad FIRST so DRAM latency overlaps the reduce
            float4 pxn = px;
            if (step < 1023) pxn = *(const float4*)(xgb + (size_t)(step + 1) * 400);
            // reduce 5 k-slice partials (LDS.128, kk-slice stride = 200 ull2)
            const ulonglong2* pp = (const ulonglong2*)(part4 + ub * 100 + uu);
            ULL sIF = pk(px.x, px.y);
            ULL sGO = pk(px.z, px.w);
#pragma unroll
            for (int kp = 0; kp < 5; kp++) {
                ulonglong2 q = pp[kp * 200];     // part4[kp][ub][uu]
                sIF = add2(sIF, q.x);
                sGO = add2(sGO, q.y);
            }
            px = pxn;
            float2 vIF = upk(sIF), vGO = upk(sGO);
            float i_ = sigf(vIF.x);
            float f_ = sigf(vIF.y);
            float g_ = tahf(vGO.x);
            float o_ = sigf(vGO.y);
            c_reg = f_ * c_reg + i_ * g_;
            float h = o_ * tahf(c_reg);
            h_last = h;
            shi[2 * uu + ub] = pk(h, h);
        }
        __syncthreads();
    }

    if (t < 200) atomicAdd(&red[ub], h_last * Wfc[uu]);
    __syncthreads();
    if (t < 2) out[b0 + t] = red[t] + bfc[0];
}

// ---------------- launch ----------------
extern "C" void kernel_launch(void* const* d_in, const int* in_sizes, int n_in,
                              void* d_out, int out_size) {
    const float* x   = (const float*)d_in[0];
    const float* h0  = (const float*)d_in[1];
    const float* c0  = (const float*)d_in[2];
    const float* Wih = (const float*)d_in[3];
    const float* Whh = (const float*)d_in[4];
    const float* bih = (const float*)d_in[5];
    const float* bhh = (const float*)d_in[6];
    const float* Wfc = (const float*)d_in[7];
    const float* bfc = (const float*)d_in[8];
    float* out = (float*)d_out;

    cudaFuncSetAttribute(xgemm_hmma, cudaFuncAttributeMaxDynamicSharedMemorySize, XS_TOT);

    prep_kernel<<<64, 256>>>(Wih, Whh, bih, bhh);
    xgemm_hmma<<<2048, 256, XS_TOT>>>(x);
    align_kernel<<<1, 32>>>();
    lstm_kernel<<<128, 512>>>(h0, c0, Wfc, bfc, out);
}

// round 16
// speedup vs baseline: 1.5472x; 1.2852x over previous
#include <cuda_runtime.h>
#include <cuda_bf16.h>
#include <cstdint>

#define ULL unsigned long long

// ---------------- scratch (static device globals; no dynamic alloc) ----------------
// xg layout: [256][1024][100][4]  (per unit u: contiguous i,f,g,o quad)
__device__ float  g_xg[104857600];
// W2hh layout: [k][2u+p] pairs; p=0 -> (W_i[u][k], W_f[u][k]); p=1 -> (W_g[u][k], W_o[u][k])
__device__ ULL    g_W2hh[100 * 200];
// B fragments for mma.sync m16n8k16 bf16: [ntile 0..49][kstep 0..3][lane 0..31]
__device__ uint4  g_Bf[50 * 4 * 32];
__device__ float4 g_bias4[100];         // per-unit (b_i, b_f, b_g, b_o), b_ih + b_hh

// ---------------- f32x2 packed helpers ----------------
__device__ __forceinline__ ULL pk(float x, float y) {
    ULL r; asm("mov.b64 %0,{%1,%2};" : "=l"(r) : "f"(x), "f"(y)); return r;
}
__device__ __forceinline__ float2 upk(ULL v) {
    float2 r; asm("mov.b64 {%0,%1},%2;" : "=f"(r.x), "=f"(r.y) : "l"(v)); return r;
}
__device__ __forceinline__ ULL fma2(ULL a, ULL b, ULL c) {
    ULL d; asm("fma.rn.f32x2 %0,%1,%2,%3;" : "=l"(d) : "l"(a), "l"(b), "l"(c)); return d;
}
__device__ __forceinline__ ULL add2(ULL a, ULL b) {
    ULL d; asm("add.rn.f32x2 %0,%1,%2;" : "=l"(d) : "l"(a), "l"(b)); return d;
}
__device__ __forceinline__ float sigf(float x) {
    float e = __expf(-x);
    return __fdividef(1.f, 1.f + e);
}
__device__ __forceinline__ float tahf(float x) {
    float e = __expf(2.f * x);
    return 1.f - __fdividef(2.f, e + 1.f);
}

// ---------------- mma / ldmatrix helpers (sm_80 baseline PTX, valid on sm_103) ----------------
__device__ __forceinline__ uint32_t bf2u(float a, float b) {
    __nv_bfloat162 h = __float22bfloat162_rn(make_float2(a, b));
    return *(uint32_t*)&h;
}
__device__ __forceinline__ void mma_bf16(float* c, const uint32_t* a, uint32_t b0, uint32_t b1) {
    asm volatile("mma.sync.aligned.m16n8k16.row.col.f32.bf16.bf16.f32 "
        "{%0,%1,%2,%3}, {%4,%5,%6,%7}, {%8,%9}, {%0,%1,%2,%3};"
        : "+f"(c[0]), "+f"(c[1]), "+f"(c[2]), "+f"(c[3])
        : "r"(a[0]), "r"(a[1]), "r"(a[2]), "r"(a[3]), "r"(b0), "r"(b1));
}
__device__ __forceinline__ void ldm4(uint32_t* r, uint32_t addr) {
    asm volatile("ldmatrix.sync.aligned.m8n8.x4.shared.b16 {%0,%1,%2,%3}, [%4];"
        : "=r"(r[0]), "=r"(r[1]), "=r"(r[2]), "=r"(r[3]) : "r"(addr));
}
__device__ __forceinline__ uint32_t smem_u32(const void* p) {
    uint32_t a;
    asm("{ .reg .u64 t; cvta.to.shared.u64 t, %1; cvt.u32.u64 %0, t; }" : "=r"(a) : "l"(p));
    return a;
}

// ---------------- prep: repack weights ----------------
__global__ void prep_kernel(const float* __restrict__ Wih, const float* __restrict__ Whh,
                            const float* __restrict__ bih, const float* __restrict__ bhh) {
    int tid = blockIdx.x * blockDim.x + threadIdx.x;
    int stride = gridDim.x * blockDim.x;
    for (int i = tid; i < 100 * 200; i += stride) {
        int k = i / 200, ju = i % 200;
        int u = ju >> 1, p = ju & 1;
        ULL v;
        if (p == 0) v = pk(Whh[(u)       * 100 + k], Whh[(100 + u) * 100 + k]);  // (i,f)
        else        v = pk(Whh[(200 + u) * 100 + k], Whh[(300 + u) * 100 + k]);  // (g,o)
        g_W2hh[i] = v;
    }
    for (int s = tid; s < 6400; s += stride) {
        int ntg = s >> 7, ks = (s >> 5) & 3, l = s & 31;
        int n = ntg * 8 + (l >> 2);
        int u = n >> 2, c = n & 3;
        const float* wr = Wih + (c * 100 + u) * 64;
        int kb = ks * 16 + (l & 3) * 2;
        float w00 = wr[kb], w01 = wr[kb + 1], w10 = wr[kb + 8], w11 = wr[kb + 9];
        __nv_bfloat16 h00 = __float2bfloat16(w00), h01 = __float2bfloat16(w01);
        __nv_bfloat16 h10 = __float2bfloat16(w10), h11 = __float2bfloat16(w11);
        uint4 o;
        o.x = bf2u(w00, w01);
        o.y = bf2u(w10, w11);
        o.z = bf2u(w00 - __bfloat162float(h00), w01 - __bfloat162float(h01));
        o.w = bf2u(w10 - __bfloat162float(h10), w11 - __bfloat162float(h11));
        g_Bf[s] = o;
    }
    for (int i = tid; i < 100; i += stride) {
        float4 v;
        v.x = bih[i]       + bhh[i];
        v.y = bih[100 + i] + bhh[100 + i];
        v.z = bih[200 + i] + bhh[200 + i];
        v.w = bih[300 + i] + bhh[300 + i];
        g_bias4[i] = v;
    }
}

// ---------------- phase 1: HMMA xgemm (bf16 hi/lo split, 3 terms) ----------------
static constexpr int XS_BF   = 0;
static constexpr int XS_AHI  = 102400;
static constexpr int XS_ALO  = 120832;
static constexpr int XS_BIAS = 139264;
static constexpr int XS_TOT  = 140864;

__global__ __launch_bounds__(256, 1) void xgemm_hmma(const float* __restrict__ x) {
    extern __shared__ char smem[];
    const int tid = threadIdx.x, warp = tid >> 5, lane = tid & 31;

    {
        uint4* dst = (uint4*)(smem + XS_BF);
        for (int i = tid; i < 6400; i += 256) dst[i] = g_Bf[i];
    }
    {
        const float* bs = (const float*)g_bias4;
        float* bd = (float*)(smem + XS_BIAS);
        for (int i = tid; i < 400; i += 256) bd[i] = bs[i];
    }
    {
        const float2* xp = (const float2*)(x + (size_t)blockIdx.x * 128 * 64);
        for (int i = tid; i < 128 * 32; i += 256) {
            int r = i >> 5, k2 = i & 31;
            float2 v = xp[i];
            uint32_t hi = bf2u(v.x, v.y);
            __nv_bfloat162 hh = *(__nv_bfloat162*)&hi;
            float2 hf = __bfloat1622float2(hh);
            uint32_t lo = bf2u(v.x - hf.x, v.y - hf.y);
            *(uint32_t*)(smem + XS_AHI + r * 144 + k2 * 4) = hi;
            *(uint32_t*)(smem + XS_ALO + r * 144 + k2 * 4) = lo;
        }
    }
    __syncthreads();

    uint32_t ah[4][4], al[4][4];
    {
        uint32_t rowoff = (uint32_t)(16 * warp + (lane & 15)) * 144 + (uint32_t)(lane >> 4) * 16;
        uint32_t sbA = smem_u32(smem);
#pragma unroll
        for (int ks = 0; ks < 4; ks++) {
            ldm4(ah[ks], sbA + XS_AHI + rowoff + ks * 32);
            ldm4(al[ks], sbA + XS_ALO + rowoff + ks * 32);
        }
    }

    const float* bs = (const float*)(smem + XS_BIAS);
    const uint4* bf = (const uint4*)(smem + XS_BF);
    size_t row0 = (size_t)blockIdx.x * 128 + warp * 16 + (lane >> 2);

#pragma unroll 1
    for (int p = 0; p < 2; p++) {
        float acc[25][4];
#pragma unroll
        for (int nt = 0; nt < 25; nt++)
#pragma unroll
            for (int q = 0; q < 4; q++) acc[nt][q] = 0.f;

#pragma unroll
        for (int ks = 0; ks < 4; ks++) {
#pragma unroll
            for (int nt = 0; nt < 25; nt++) {
                uint4 b = bf[((p * 25 + nt) * 4 + ks) * 32 + lane];
                mma_bf16(acc[nt], ah[ks], b.x, b.y);
                mma_bf16(acc[nt], ah[ks], b.z, b.w);
                mma_bf16(acc[nt], al[ks], b.x, b.y);
            }
        }
#pragma unroll
        for (int nt = 0; nt < 25; nt++) {
            int col = p * 200 + nt * 8 + (lane & 3) * 2;
            float bx = bs[col], by = bs[col + 1];
            *(float2*)(g_xg + row0 * 400 + col)       = make_float2(acc[nt][0] + bx, acc[nt][1] + by);
            *(float2*)(g_xg + (row0 + 8) * 400 + col) = make_float2(acc[nt][2] + bx, acc[nt][3] + by);
        }
    }
}

// no-op: keeps the launch cycle length 4 so ncu's capture window lands on lstm_kernel.
__global__ void align_kernel() {}

// ---------------- phase 2: sequential LSTM recurrence + fused FC head ----------------
// EXACT R13 structure (measured 1088 us). 128 blocks x 512 threads; thread
// (kk=t/100, u=t%100) does k-slice [20kk,20kk+20) of unit u's gate pairs for
// both batches, W slice in 80 regs, h broadcast via LDS.128 dup-pairs.
// Pointwise threads (t<200) reduce 5 partials then prefetch xg. 2 barriers/step.
__global__ __launch_bounds__(512, 1) void lstm_kernel(const float* __restrict__ h0,
                                                      const float* __restrict__ c0,
                                                      const float* __restrict__ Wfc,
                                                      const float* __restrict__ bfc,
                                                      float* __restrict__ out) {
    __shared__ __align__(16) ULL shi[200];            // [k][b]: shi[2k+b] = pk(h_b[k], h_b[k])
    __shared__ __align__(16) float4 part4[5 * 2 * 100];  // [kk][b][u] = (i,f,g,o) partial
    __shared__ float red[2];                          // FC reduction

    const int t  = threadIdx.x;
    const int b0 = blockIdx.x * 2;

    const bool mv = (t < 500);
    const int kk = t / 100;
    const int u  = t % 100;
    const int k0 = kk * 20;

    ULL wIF[20], wGO[20];
    if (mv) {
#pragma unroll
        for (int kc = 0; kc < 20; kc++) {
            wIF[kc] = g_W2hh[(k0 + kc) * 200 + 2 * u];
            wGO[kc] = g_W2hh[(k0 + kc) * 200 + 2 * u + 1];
        }
    }

    const int ub = (t < 100) ? 0 : 1;
    const int uu = t - ub * 100;

    if (t < 2) red[t] = 0.f;

    float c_reg = 0.f, h_last = 0.f;
    float4 px = make_float4(0.f, 0.f, 0.f, 0.f);
    const float* xgb = g_xg;
    if (t < 200) {
        float hv = h0[(b0 + ub) * 100 + uu];
        c_reg    = c0[(b0 + ub) * 100 + uu];
        shi[2 * uu + ub] = pk(hv, hv);
        xgb = g_xg + (size_t)(b0 + ub) * 1024 * 400 + 4 * uu;
        px = *(const float4*)xgb;
    }
    __syncthreads();

    float4* pb0 = part4 + kk * 200 + u;
    float4* pb1 = pb0 + 100;
    const ulonglong2* hp = ((const ulonglong2*)shi) + k0;

    for (int step = 0; step < 1024; step++) {
        if (mv) {
            ULL aIF0 = 0ull, aGO0 = 0ull, aIF1 = 0ull, aGO1 = 0ull;
#pragma unroll
            for (int kc = 0; kc < 20; kc++) {
                ulonglong2 hv = hp[kc];
                aIF0 = fma2(wIF[kc], hv.x, aIF0);
                aGO0 = fma2(wGO[kc], hv.x, aGO0);
                aIF1 = fma2(wIF[kc], hv.y, aIF1);
                aGO1 = fma2(wGO[kc], hv.y, aGO1);
            }
            float2 pif = upk(aIF0), pgo = upk(aGO0);
            *pb0 = make_float4(pif.x, pif.y, pgo.x, pgo.y);
            pif = upk(aIF1); pgo = upk(aGO1);
            *pb1 = make_float4(pif.x, pif.y, pgo.x, pgo.y);
        }
        __syncthreads();
        if (t < 200) {
            // part4 as ulonglong2*: one float4 == one ull2 -> kk-slice stride = 200
            const ulonglong2* pp = (const ulonglong2*)(part4 + ub * 100 + uu);
            ULL sIF = pk(px.x, px.y);
            ULL sGO = pk(px.z, px.w);
#pragma unroll
            for (int kp = 0; kp < 5; kp++) {
                ulonglong2 q = pp[kp * 200];     // part4[kp][ub][uu]
                sIF = add2(sIF, q.x);
                sGO = add2(sGO, q.y);
            }
            if (step < 1023) {
                px = *(const float4*)(xgb + (size_t)(step + 1) * 400);
            }
            float2 vIF = upk(sIF), vGO = upk(sGO);
            float i_ = sigf(vIF.x);
            float f_ = sigf(vIF.y);
            float g_ = tahf(vGO.x);
            float o_ = sigf(vGO.y);
            c_reg = f_ * c_reg + i_ * g_;
            float h = o_ * tahf(c_reg);
            h_last = h;
            shi[2 * uu + ub] = pk(h, h);
        }
        __syncthreads();
    }

    if (t < 200) atomicAdd(&red[ub], h_last * Wfc[uu]);
    __syncthreads();
    if (t < 2) out[b0 + t] = red[t] + bfc[0];
}

// ---------------- launch ----------------
extern "C" void kernel_launch(void* const* d_in, const int* in_sizes, int n_in,
                              void* d_out, int out_size) {
    const float* x   = (const float*)d_in[0];
    const float* h0  = (const float*)d_in[1];
    const float* c0  = (const float*)d_in[2];
    const float* Wih = (const float*)d_in[3];
    const float* Whh = (const float*)d_in[4];
    const float* bih = (const float*)d_in[5];
    const float* bhh = (const float*)d_in[6];
    const float* Wfc = (const float*)d_in[7];
    const float* bfc = (const float*)d_in[8];
    float* out = (float*)d_out;

    cudaFuncSetAttribute(xgemm_hmma, cudaFuncAttributeMaxDynamicSharedMemorySize, XS_TOT);

    prep_kernel<<<64, 256>>>(Wih, Whh, bih, bhh);
    xgemm_hmma<<<2048, 256, XS_TOT>>>(x);
    align_kernel<<<1, 32>>>();
    lstm_kernel<<<128, 512>>>(h0, c0, Wfc, bfc, out);
}